// round 3
// baseline (speedup 1.0000x reference)
#include <cuda_runtime.h>
#include <math.h>

#define NT 1024
#define DN 256
#define DE 128
#define DBS 64
#define DHD 48
#define NH 8
#define DQKV 1536
#define INFV 1000000.0f
#define EPSV 1e-5f
#define SCALEQ 0.0625f

struct Scratch {
    float node_n[NT * DN];
    float Wcat[DN * DQKV];
    float qkvg[NT * DQKV];
    float gated[NT * (NH * DHD)];
    float attnout[NT * DN];
    float h0[NT * DN];
    float h1[NT * 2 * DN];
    float Wgb[DE * NH];
    float WbWb[DBS * NH];
    float csum[NH];
    float cb[NH];
    float bterm[(size_t)NT * NH * NT];
    float S[(size_t)NT * NH * NT];
};
__device__ Scratch g_s;

// ---------- tiny precompute: Wgb = g_edge*Wb ; WbWb = W_bias@Wb ; csum, cb ----------
__global__ __launch_bounds__(256) void precompute_kernel(
    const float* __restrict__ ge, const float* __restrict__ be,
    const float* __restrict__ W_bias, const float* __restrict__ Wb)
{
    int t = threadIdx.x;
    if (t < DE) {
        float g = ge[t];
#pragma unroll
        for (int h = 0; h < NH; h++) g_s.Wgb[t * NH + h] = g * Wb[t * NH + h];
    } else if (t - DE < DBS) {
        int d = t - DE;
        float acc[NH] = {};
        for (int c = 0; c < DE; c++) {
            float w = W_bias[d * DE + c];
#pragma unroll
            for (int h = 0; h < NH; h++) acc[h] += w * Wb[c * NH + h];
        }
#pragma unroll
        for (int h = 0; h < NH; h++) g_s.WbWb[d * NH + h] = acc[h];
    }
    __syncthreads();
    if (t < NH) {
        float cs = 0.f, cbv = 0.f;
        for (int c = 0; c < DE; c++) {
            cs += g_s.Wgb[c * NH + t];
            cbv += be[c] * Wb[c * NH + t];
        }
        g_s.csum[t] = cs; g_s.cb[t] = cbv;
    }
}

// ---------- pack [Wq|Wk|Wv|Wg] -> (256 x 1536) ----------
__global__ __launch_bounds__(256) void packw_kernel(
    const float* __restrict__ Wq, const float* __restrict__ Wk,
    const float* __restrict__ Wv, const float* __restrict__ Wg)
{
    int idx = blockIdx.x * 256 + threadIdx.x;
    if (idx >= DN * DQKV) return;
    int k = idx / DQKV, j = idx % DQKV;
    int sel = j / 384, jc = j - sel * 384;
    const float* src = (sel == 0) ? Wq : (sel == 1) ? Wk : (sel == 2) ? Wv : Wg;
    g_s.Wcat[idx] = src[k * 384 + jc];
}

// ---------- LayerNorm D=256, one warp per row ----------
__global__ __launch_bounds__(256) void ln_kernel(
    const float* __restrict__ x, const float* __restrict__ gamma,
    const float* __restrict__ beta, float* __restrict__ out)
{
    int warp = threadIdx.x >> 5, lane = threadIdx.x & 31;
    size_t row = (size_t)blockIdx.x * 8 + warp;
    const float4* x4 = (const float4*)(x + row * DN);
    float4 v[2]; float s1 = 0.f, s2 = 0.f;
#pragma unroll
    for (int u = 0; u < 2; u++) {
        v[u] = x4[lane + u * 32];
        s1 += v[u].x + v[u].y + v[u].z + v[u].w;
        s2 += v[u].x*v[u].x + v[u].y*v[u].y + v[u].z*v[u].z + v[u].w*v[u].w;
    }
#pragma unroll
    for (int o = 16; o >= 1; o >>= 1) {
        s1 += __shfl_xor_sync(0xffffffffu, s1, o);
        s2 += __shfl_xor_sync(0xffffffffu, s2, o);
    }
    float m = s1 * (1.f / DN);
    float rs = rsqrtf(s2 * (1.f / DN) - m * m + EPSV);
    const float4* g4 = (const float4*)gamma;
    const float4* b4 = (const float4*)beta;
    float4* o4 = (float4*)(out + row * DN);
#pragma unroll
    for (int u = 0; u < 2; u++) {
        int c = lane + u * 32;
        float4 g = g4[c], b = b4[c], r;
        r.x = (v[u].x - m) * rs * g.x + b.x;
        r.y = (v[u].y - m) * rs * g.y + b.y;
        r.z = (v[u].z - m) * rs * g.z + b.z;
        r.w = (v[u].w - m) * rs * g.w + b.w;
        o4[c] = r;
    }
}

// ---------- fused edge-LN + bias-proj -> b_term[i][h][j] (heavy, HBM-bound) ----------
__global__ __launch_bounds__(256) void bterm_kernel(
    const float* __restrict__ edge, const float* __restrict__ bias)
{
    __shared__ float sWgb[DE * NH];
    __shared__ float sWbb[DBS * NH];
    __shared__ float sCsum[NH], sCb[NH];
    __shared__ float stage[32 * 9];
    int tid = threadIdx.x;
    for (int u = tid; u < DE * NH; u += 256) sWgb[u] = g_s.Wgb[u];
    for (int u = tid; u < DBS * NH; u += 256) sWbb[u] = g_s.WbWb[u];
    if (tid < NH) { sCsum[tid] = g_s.csum[tid]; sCb[tid] = g_s.cb[tid]; }
    __syncthreads();

    int warp = tid >> 5, lane = tid & 31;
    int g = lane >> 3, l = lane & 7;            // 4 pairs/warp, 8 lanes/pair
    size_t p = (size_t)blockIdx.x * 32 + warp * 4 + g;

    const float4* e4 = (const float4*)(edge + p * DE);
    float4 ev[4];
#pragma unroll
    for (int u = 0; u < 4; u++) ev[u] = e4[u * 8 + l];   // coalesced
    const float4* b4 = (const float4*)(bias + p * DBS);
    float4 bv0 = b4[l], bv1 = b4[l + 8];

    float s1 = 0.f, s2 = 0.f;
#pragma unroll
    for (int u = 0; u < 4; u++) {
        s1 += ev[u].x + ev[u].y + ev[u].z + ev[u].w;
        s2 += ev[u].x*ev[u].x + ev[u].y*ev[u].y + ev[u].z*ev[u].z + ev[u].w*ev[u].w;
    }
    float dh[8] = {}, bdh[8] = {};
    const float4* w4 = (const float4*)sWgb;
#pragma unroll
    for (int u = 0; u < 4; u++) {
        float es[4] = {ev[u].x, ev[u].y, ev[u].z, ev[u].w};
#pragma unroll
        for (int q = 0; q < 4; q++) {
            int c = (u * 8 + l) * 4 + q;
            float e = es[q];
            float4 w0 = w4[c * 2], w1 = w4[c * 2 + 1];
            dh[0] += e*w0.x; dh[1] += e*w0.y; dh[2] += e*w0.z; dh[3] += e*w0.w;
            dh[4] += e*w1.x; dh[5] += e*w1.y; dh[6] += e*w1.z; dh[7] += e*w1.w;
        }
    }
    {
        const float4* wb4 = (const float4*)sWbb;
        float bs[8] = {bv0.x, bv0.y, bv0.z, bv0.w, bv1.x, bv1.y, bv1.z, bv1.w};
#pragma unroll
        for (int q = 0; q < 8; q++) {
            int c = (q < 4) ? (4 * l + q) : (32 + 4 * l + q - 4);
            float e = bs[q];
            float4 w0 = wb4[c * 2], w1 = wb4[c * 2 + 1];
            bdh[0] += e*w0.x; bdh[1] += e*w0.y; bdh[2] += e*w0.z; bdh[3] += e*w0.w;
            bdh[4] += e*w1.x; bdh[5] += e*w1.y; bdh[6] += e*w1.z; bdh[7] += e*w1.w;
        }
    }
#pragma unroll
    for (int o = 4; o >= 1; o >>= 1) {
        s1 += __shfl_xor_sync(0xffffffffu, s1, o);
        s2 += __shfl_xor_sync(0xffffffffu, s2, o);
    }
    float m = s1 * (1.f / DE);
    float rs = rsqrtf(s2 * (1.f / DE) - m * m + EPSV);
#pragma unroll
    for (int h = 0; h < 8; h++) {
        float tt = rs * dh[h] + bdh[h];
#pragma unroll
        for (int o = 4; o >= 1; o >>= 1)
            tt += __shfl_xor_sync(0xffffffffu, tt, o);
        if (l == 0) stage[(warp * 4 + g) * 9 + h] = tt - rs * m * sCsum[h] + sCb[h];
    }
    __syncthreads();
    int jj = tid & 31, h = tid >> 5;
    size_t base = (size_t)blockIdx.x * 32;
    int i = (int)(base >> 10), jb = (int)(base & 1023);
    g_s.bterm[((size_t)i * NH + h) * NT + jb + jj] = stage[jj * 9 + h];
}

// ---------- generic 64x64 fp32 GEMM; EPI 0=none 1=qkvg-gate 2=bias+relu 3=bias+residual ----------
template <int EPI>
__global__ __launch_bounds__(256) void gemm_kernel(
    const float* __restrict__ A, const float* __restrict__ B, float* __restrict__ C,
    int M, int N, int K, const float* __restrict__ bias_v, const float* __restrict__ extra)
{
    __shared__ float As[64][33];
    __shared__ float Bs[32][64];
    int tx = threadIdx.x & 15, ty = threadIdx.x >> 4;
    int j0 = blockIdx.x * 64, i0 = blockIdx.y * 64;
    float acc[4][4] = {};
    for (int kt = 0; kt < K; kt += 32) {
#pragma unroll
        for (int u = 0; u < 2; u++) {
            int idx = threadIdx.x * 2 + u;
            int r = idx >> 3, c4 = (idx & 7) * 4;
            float4 a = *(const float4*)(A + (size_t)(i0 + r) * K + kt + c4);
            As[r][c4] = a.x; As[r][c4+1] = a.y; As[r][c4+2] = a.z; As[r][c4+3] = a.w;
            int rb = idx >> 4, cb4 = (idx & 15) * 4;
            *(float4*)&Bs[rb][cb4] = *(const float4*)(B + (size_t)(kt + rb) * N + j0 + cb4);
        }
        __syncthreads();
#pragma unroll
        for (int kk = 0; kk < 32; kk++) {
            float a0 = As[ty*4][kk], a1 = As[ty*4+1][kk], a2 = As[ty*4+2][kk], a3 = As[ty*4+3][kk];
            float4 b = *(float4*)&Bs[kk][tx * 4];
            acc[0][0]+=a0*b.x; acc[0][1]+=a0*b.y; acc[0][2]+=a0*b.z; acc[0][3]+=a0*b.w;
            acc[1][0]+=a1*b.x; acc[1][1]+=a1*b.y; acc[1][2]+=a1*b.z; acc[1][3]+=a1*b.w;
            acc[2][0]+=a2*b.x; acc[2][1]+=a2*b.y; acc[2][2]+=a2*b.z; acc[2][3]+=a2*b.w;
            acc[3][0]+=a3*b.x; acc[3][1]+=a3*b.y; acc[3][2]+=a3*b.z; acc[3][3]+=a3*b.w;
        }
        __syncthreads();
    }
#pragma unroll
    for (int mm = 0; mm < 4; mm++) {
        int i = i0 + ty * 4 + mm, j = j0 + tx * 4;
        float vv[4] = {acc[mm][0], acc[mm][1], acc[mm][2], acc[mm][3]};
#pragma unroll
        for (int n = 0; n < 4; n++) {
            float v = vv[n]; int jc = j + n;
            if (EPI == 1) {
                if (jc >= 1152) { v += bias_v[jc - 1152]; v = 1.f / (1.f + __expf(-v)); }
            } else if (EPI == 2) {
                v = fmaxf(v + bias_v[jc], 0.f);
            } else if (EPI == 3) {
                v = v + bias_v[jc] + extra[(size_t)i * N + jc];
            }
            vv[n] = v;
        }
        float4 r; r.x = vv[0]; r.y = vv[1]; r.z = vv[2]; r.w = vv[3];
        *(float4*)(C + (size_t)i * N + j) = r;
    }
}

// ---------- RoPE on q,k slices (in place), double trig ----------
__global__ __launch_bounds__(256) void rope_kernel(const float* __restrict__ pos)
{
    int idx = blockIdx.x * 256 + threadIdx.x;
    if (idx >= NT * NH * 24) return;
    int t = idx % 24, h = (idx / 24) % NH, i = idx / (24 * NH);
    double invf = exp(-(double)t * (9.210340371976184 / 24.0));
    double th = (double)pos[i] * invf;
    float c = (float)cos(th), s = (float)sin(th);
    size_t bq = (size_t)i * DQKV + h * DHD;
    float x1 = g_s.qkvg[bq + t], x2 = g_s.qkvg[bq + 24 + t];
    g_s.qkvg[bq + t] = x1 * c - x2 * s;
    g_s.qkvg[bq + 24 + t] = x1 * s + x2 * c;
    size_t bk = bq + 384;
    x1 = g_s.qkvg[bk + t]; x2 = g_s.qkvg[bk + 24 + t];
    g_s.qkvg[bk + t] = x1 * c - x2 * s;
    g_s.qkvg[bk + 24 + t] = x1 * s + x2 * c;
}

// ---------- S = scale*q.k + bterm + mask ----------
__global__ __launch_bounds__(256) void qk_kernel(const float* __restrict__ mask)
{
    __shared__ float Qs[64][49];
    __shared__ float Kt[48][68];
    int h = blockIdx.z, i0 = blockIdx.y * 64, j0 = blockIdx.x * 64;
    for (int u = threadIdx.x; u < 64 * 48; u += 256) {
        int r = u / 48, d = u % 48;
        Qs[r][d] = g_s.qkvg[(size_t)(i0 + r) * DQKV + h * DHD + d];
        Kt[d][r] = g_s.qkvg[(size_t)(j0 + r) * DQKV + 384 + h * DHD + d];
    }
    __syncthreads();
    int tx = threadIdx.x & 15, ty = threadIdx.x >> 4;
    float acc[4][4] = {};
#pragma unroll
    for (int d = 0; d < 48; d++) {
        float a0 = Qs[ty*4][d], a1 = Qs[ty*4+1][d], a2 = Qs[ty*4+2][d], a3 = Qs[ty*4+3][d];
        float4 b = *(float4*)&Kt[d][tx * 4];
        acc[0][0]+=a0*b.x; acc[0][1]+=a0*b.y; acc[0][2]+=a0*b.z; acc[0][3]+=a0*b.w;
        acc[1][0]+=a1*b.x; acc[1][1]+=a1*b.y; acc[1][2]+=a1*b.z; acc[1][3]+=a1*b.w;
        acc[2][0]+=a2*b.x; acc[2][1]+=a2*b.y; acc[2][2]+=a2*b.z; acc[2][3]+=a2*b.w;
        acc[3][0]+=a3*b.x; acc[3][1]+=a3*b.y; acc[3][2]+=a3*b.z; acc[3][3]+=a3*b.w;
    }
    int j = j0 + tx * 4;
    float mj0 = mask[j], mj1 = mask[j+1], mj2 = mask[j+2], mj3 = mask[j+3];
#pragma unroll
    for (int mm = 0; mm < 4; mm++) {
        int i = i0 + ty * 4 + mm;
        float mi = mask[i];
        size_t rowb = ((size_t)i * NH + h) * NT + j;
        float4 bt = *(const float4*)&g_s.bterm[rowb];
        float4 r;
        r.x = acc[mm][0]*SCALEQ + bt.x + INFV*(mi*mj0 - 1.f);
        r.y = acc[mm][1]*SCALEQ + bt.y + INFV*(mi*mj1 - 1.f);
        r.z = acc[mm][2]*SCALEQ + bt.z + INFV*(mi*mj2 - 1.f);
        r.w = acc[mm][3]*SCALEQ + bt.w + INFV*(mi*mj3 - 1.f);
        *(float4*)&g_s.S[rowb] = r;
    }
}

// ---------- row softmax over j (in place), one warp per (i,h) ----------
__global__ __launch_bounds__(256) void softmax_kernel()
{
    int warp = threadIdx.x >> 5, lane = threadIdx.x & 31;
    size_t row = (size_t)blockIdx.x * 8 + warp;
    float4* p4 = (float4*)(g_s.S + row * NT);
    float4 v[8]; float mx = -1e30f;
#pragma unroll
    for (int u = 0; u < 8; u++) {
        v[u] = p4[lane + u * 32];
        mx = fmaxf(mx, fmaxf(fmaxf(v[u].x, v[u].y), fmaxf(v[u].z, v[u].w)));
    }
#pragma unroll
    for (int o = 16; o >= 1; o >>= 1)
        mx = fmaxf(mx, __shfl_xor_sync(0xffffffffu, mx, o));
    float sum = 0.f;
#pragma unroll
    for (int u = 0; u < 8; u++) {
        v[u].x = __expf(v[u].x - mx); v[u].y = __expf(v[u].y - mx);
        v[u].z = __expf(v[u].z - mx); v[u].w = __expf(v[u].w - mx);
        sum += v[u].x + v[u].y + v[u].z + v[u].w;
    }
#pragma unroll
    for (int o = 16; o >= 1; o >>= 1)
        sum += __shfl_xor_sync(0xffffffffu, sum, o);
    float inv = 1.f / sum;
#pragma unroll
    for (int u = 0; u < 8; u++) {
        v[u].x *= inv; v[u].y *= inv; v[u].z *= inv; v[u].w *= inv;
        p4[lane + u * 32] = v[u];
    }
}

// ---------- out = P @ V, gated; 64 i x 48 d tile per block per head ----------
__global__ __launch_bounds__(256) void av_kernel()
{
    __shared__ float Ps[64][33];
    __shared__ float Vs[32][49];
    int h = blockIdx.z, i0 = blockIdx.y * 64;
    int tx = threadIdx.x & 15, ty = threadIdx.x >> 4;
    float acc[4][3] = {};
    for (int kt = 0; kt < NT; kt += 32) {
#pragma unroll
        for (int u = 0; u < 8; u++) {
            int idx = threadIdx.x + u * 256;
            int r = idx >> 5, c = idx & 31;
            Ps[r][c] = g_s.S[((size_t)(i0 + r) * NH + h) * NT + kt + c];
        }
#pragma unroll
        for (int u = 0; u < 6; u++) {
            int idx = threadIdx.x + u * 256;
            int r = idx / 48, c = idx % 48;
            Vs[r][c] = g_s.qkvg[(size_t)(kt + r) * DQKV + 768 + h * DHD + c];
        }
        __syncthreads();
#pragma unroll
        for (int kk = 0; kk < 32; kk++) {
            float b0 = Vs[kk][tx*3], b1 = Vs[kk][tx*3+1], b2 = Vs[kk][tx*3+2];
#pragma unroll
            for (int mm = 0; mm < 4; mm++) {
                float a = Ps[ty * 4 + mm][kk];
                acc[mm][0] += a * b0; acc[mm][1] += a * b1; acc[mm][2] += a * b2;
            }
        }
        __syncthreads();
    }
#pragma unroll
    for (int mm = 0; mm < 4; mm++) {
        int i = i0 + ty * 4 + mm;
#pragma unroll
        for (int n = 0; n < 3; n++) {
            int d = tx * 3 + n;
            float gate = g_s.qkvg[(size_t)i * DQKV + 1152 + h * DHD + d];
            g_s.gated[(size_t)i * (NH * DHD) + h * DHD + d] = gate * acc[mm][n];
        }
    }
}

extern "C" void kernel_launch(void* const* d_in, const int* in_sizes, int n_in,
                              void* d_out, int out_size)
{
    const float* node   = (const float*)d_in[0];
    const float* edge   = (const float*)d_in[1];
    const float* bias   = (const float*)d_in[2];
    const float* pos    = (const float*)d_in[3];
    const float* mask   = (const float*)d_in[4];
    const float* g_node = (const float*)d_in[5];
    const float* b_node = (const float*)d_in[6];
    const float* g_edge = (const float*)d_in[7];
    const float* b_edge = (const float*)d_in[8];
    const float* W_bias = (const float*)d_in[9];
    const float* Wq     = (const float*)d_in[10];
    const float* Wk     = (const float*)d_in[11];
    const float* Wv     = (const float*)d_in[12];
    const float* Wb     = (const float*)d_in[13];
    const float* Wg     = (const float*)d_in[14];
    const float* bg     = (const float*)d_in[15];
    const float* Wo     = (const float*)d_in[16];
    const float* g_ff   = (const float*)d_in[17];
    const float* b_ff   = (const float*)d_in[18];
    const float* W1     = (const float*)d_in[19];
    const float* b1     = (const float*)d_in[20];
    const float* W2     = (const float*)d_in[21];
    const float* b2     = (const float*)d_in[22];
    float* out = (float*)d_out;

    Scratch* s = nullptr;
    cudaGetSymbolAddress((void**)&s, g_s);

    precompute_kernel<<<1, 256>>>(g_edge, b_edge, W_bias, Wb);
    packw_kernel<<<(DN * DQKV + 255) / 256, 256>>>(Wq, Wk, Wv, Wg);
    ln_kernel<<<NT / 8, 256>>>(node, g_node, b_node, s->node_n);
    gemm_kernel<1><<<dim3(DQKV / 64, NT / 64), 256>>>(s->node_n, s->Wcat, s->qkvg,
                                                      NT, DQKV, DN, bg, nullptr);
    rope_kernel<<<(NT * NH * 24 + 255) / 256, 256>>>(pos);
    bterm_kernel<<<(NT * NT) / 32, 256>>>(edge, bias);
    qk_kernel<<<dim3(NT / 64, NT / 64, NH), 256>>>(mask);
    softmax_kernel<<<(NT * NH) / 8, 256>>>();
    av_kernel<<<dim3(1, NT / 64, NH), 256>>>();
    gemm_kernel<0><<<dim3(DN / 64, NT / 64), 256>>>(s->gated, Wo, s->attnout,
                                                    NT, DN, NH * DHD, nullptr, nullptr);
    ln_kernel<<<NT / 8, 256>>>(s->attnout, g_ff, b_ff, s->h0);
    gemm_kernel<2><<<dim3(2 * DN / 64, NT / 64), 256>>>(s->h0, W1, s->h1,
                                                        NT, 2 * DN, DN, b1, nullptr);
    gemm_kernel<3><<<dim3(DN / 64, NT / 64), 256>>>(s->h1, W2, out,
                                                    NT, DN, 2 * DN, b2, node);
}

// round 5
// speedup vs baseline: 1.0108x; 1.0108x over previous
#include <cuda_runtime.h>
#include <math.h>

#define NT 1024
#define DN 256
#define DE 128
#define DBS 64
#define DHD 48
#define NH 8
#define DQKV 1536
#define INFV 1000000.0f
#define EPSV 1e-5f
#define SCALEQ 0.0625f

struct Scratch {
    float node_n[NT * DN];
    float Wcat[DN * DQKV];
    float qkvg[NT * DQKV];
    float gated[NT * (NH * DHD)];
    float attnout[NT * DN];
    float h0[NT * DN];
    float h1[NT * 2 * DN];
    float Wgb[DE * NH];
    float WbWb[DBS * NH];
    float csum[NH];
    float cb[NH];
    float bterm[(size_t)NT * NH * NT];
};
__device__ Scratch g_s;

// ---------- tiny precompute: Wgb = g_edge*Wb ; WbWb = W_bias@Wb ; csum, cb ----------
__global__ __launch_bounds__(256) void precompute_kernel(
    const float* __restrict__ ge, const float* __restrict__ be,
    const float* __restrict__ W_bias, const float* __restrict__ Wb)
{
    int t = threadIdx.x;
    if (t < DE) {
        float g = ge[t];
#pragma unroll
        for (int h = 0; h < NH; h++) g_s.Wgb[t * NH + h] = g * Wb[t * NH + h];
    } else if (t - DE < DBS) {
        int d = t - DE;
        float acc[NH] = {};
        for (int c = 0; c < DE; c++) {
            float w = W_bias[d * DE + c];
#pragma unroll
            for (int h = 0; h < NH; h++) acc[h] += w * Wb[c * NH + h];
        }
#pragma unroll
        for (int h = 0; h < NH; h++) g_s.WbWb[d * NH + h] = acc[h];
    }
    __syncthreads();
    if (t < NH) {
        float cs = 0.f, cbv = 0.f;
        for (int c = 0; c < DE; c++) {
            cs += g_s.Wgb[c * NH + t];
            cbv += be[c] * Wb[c * NH + t];
        }
        g_s.csum[t] = cs; g_s.cb[t] = cbv;
    }
}

// ---------- pack [Wq|Wk|Wv|Wg] -> (256 x 1536) ----------
__global__ __launch_bounds__(256) void packw_kernel(
    const float* __restrict__ Wq, const float* __restrict__ Wk,
    const float* __restrict__ Wv, const float* __restrict__ Wg)
{
    int idx = blockIdx.x * 256 + threadIdx.x;
    if (idx >= DN * DQKV) return;
    int k = idx / DQKV, j = idx % DQKV;
    int sel = j / 384, jc = j - sel * 384;
    const float* src = (sel == 0) ? Wq : (sel == 1) ? Wk : (sel == 2) ? Wv : Wg;
    g_s.Wcat[idx] = src[k * 384 + jc];
}

// ---------- LayerNorm D=256, one warp per row ----------
__global__ __launch_bounds__(256) void ln_kernel(
    const float* __restrict__ x, const float* __restrict__ gamma,
    const float* __restrict__ beta, float* __restrict__ out)
{
    int warp = threadIdx.x >> 5, lane = threadIdx.x & 31;
    size_t row = (size_t)blockIdx.x * 8 + warp;
    const float4* x4 = (const float4*)(x + row * DN);
    float4 v[2]; float s1 = 0.f, s2 = 0.f;
#pragma unroll
    for (int u = 0; u < 2; u++) {
        v[u] = x4[lane + u * 32];
        s1 += v[u].x + v[u].y + v[u].z + v[u].w;
        s2 += v[u].x*v[u].x + v[u].y*v[u].y + v[u].z*v[u].z + v[u].w*v[u].w;
    }
#pragma unroll
    for (int o = 16; o >= 1; o >>= 1) {
        s1 += __shfl_xor_sync(0xffffffffu, s1, o);
        s2 += __shfl_xor_sync(0xffffffffu, s2, o);
    }
    float m = s1 * (1.f / DN);
    float rs = rsqrtf(s2 * (1.f / DN) - m * m + EPSV);
    const float4* g4 = (const float4*)gamma;
    const float4* b4 = (const float4*)beta;
    float4* o4 = (float4*)(out + row * DN);
#pragma unroll
    for (int u = 0; u < 2; u++) {
        int c = lane + u * 32;
        float4 g = g4[c], b = b4[c], r;
        r.x = (v[u].x - m) * rs * g.x + b.x;
        r.y = (v[u].y - m) * rs * g.y + b.y;
        r.z = (v[u].z - m) * rs * g.z + b.z;
        r.w = (v[u].w - m) * rs * g.w + b.w;
        o4[c] = r;
    }
}

// ---------- fused edge-LN + bias-proj -> b_term[i][h][j] (heavy, HBM-bound) ----------
__global__ __launch_bounds__(256) void bterm_kernel(
    const float* __restrict__ edge, const float* __restrict__ bias)
{
    __shared__ float sWgb[DE * NH];
    __shared__ float sWbb[DBS * NH];
    __shared__ float sCsum[NH], sCb[NH];
    __shared__ float stage[32 * 9];
    int tid = threadIdx.x;
    for (int u = tid; u < DE * NH; u += 256) sWgb[u] = g_s.Wgb[u];
    for (int u = tid; u < DBS * NH; u += 256) sWbb[u] = g_s.WbWb[u];
    if (tid < NH) { sCsum[tid] = g_s.csum[tid]; sCb[tid] = g_s.cb[tid]; }
    __syncthreads();

    int warp = tid >> 5, lane = tid & 31;
    int g = lane >> 3, l = lane & 7;            // 4 pairs/warp, 8 lanes/pair
    size_t p = (size_t)blockIdx.x * 32 + warp * 4 + g;

    const float4* e4 = (const float4*)(edge + p * DE);
    float4 ev[4];
#pragma unroll
    for (int u = 0; u < 4; u++) ev[u] = e4[u * 8 + l];   // coalesced
    const float4* b4 = (const float4*)(bias + p * DBS);
    float4 bv0 = b4[l], bv1 = b4[l + 8];

    float s1 = 0.f, s2 = 0.f;
#pragma unroll
    for (int u = 0; u < 4; u++) {
        s1 += ev[u].x + ev[u].y + ev[u].z + ev[u].w;
        s2 += ev[u].x*ev[u].x + ev[u].y*ev[u].y + ev[u].z*ev[u].z + ev[u].w*ev[u].w;
    }
    float dh[8] = {}, bdh[8] = {};
    const float4* w4 = (const float4*)sWgb;
#pragma unroll
    for (int u = 0; u < 4; u++) {
        float es[4] = {ev[u].x, ev[u].y, ev[u].z, ev[u].w};
#pragma unroll
        for (int q = 0; q < 4; q++) {
            int c = (u * 8 + l) * 4 + q;
            float e = es[q];
            float4 w0 = w4[c * 2], w1 = w4[c * 2 + 1];
            dh[0] += e*w0.x; dh[1] += e*w0.y; dh[2] += e*w0.z; dh[3] += e*w0.w;
            dh[4] += e*w1.x; dh[5] += e*w1.y; dh[6] += e*w1.z; dh[7] += e*w1.w;
        }
    }
    {
        const float4* wb4 = (const float4*)sWbb;
        float bs[8] = {bv0.x, bv0.y, bv0.z, bv0.w, bv1.x, bv1.y, bv1.z, bv1.w};
#pragma unroll
        for (int q = 0; q < 8; q++) {
            int c = (q < 4) ? (4 * l + q) : (32 + 4 * l + q - 4);
            float e = bs[q];
            float4 w0 = wb4[c * 2], w1 = wb4[c * 2 + 1];
            bdh[0] += e*w0.x; bdh[1] += e*w0.y; bdh[2] += e*w0.z; bdh[3] += e*w0.w;
            bdh[4] += e*w1.x; bdh[5] += e*w1.y; bdh[6] += e*w1.z; bdh[7] += e*w1.w;
        }
    }
#pragma unroll
    for (int o = 4; o >= 1; o >>= 1) {
        s1 += __shfl_xor_sync(0xffffffffu, s1, o);
        s2 += __shfl_xor_sync(0xffffffffu, s2, o);
    }
    float m = s1 * (1.f / DE);
    float rs = rsqrtf(s2 * (1.f / DE) - m * m + EPSV);
#pragma unroll
    for (int h = 0; h < 8; h++) {
        float tt = rs * dh[h] + bdh[h];
#pragma unroll
        for (int o = 4; o >= 1; o >>= 1)
            tt += __shfl_xor_sync(0xffffffffu, tt, o);
        if (l == 0) stage[(warp * 4 + g) * 9 + h] = tt - rs * m * sCsum[h] + sCb[h];
    }
    __syncthreads();
    int jj = tid & 31, h = tid >> 5;
    size_t base = (size_t)blockIdx.x * 32;
    int i = (int)(base >> 10), jb = (int)(base & 1023);
    g_s.bterm[((size_t)i * NH + h) * NT + jb + jj] = stage[jj * 9 + h];
}

// ---------- generic 64x64 fp32 GEMM; EPI 0=none 1=qkvg-gate 2=bias+relu 3=bias+residual ----------
template <int EPI>
__global__ __launch_bounds__(256) void gemm_kernel(
    const float* __restrict__ A, const float* __restrict__ B, float* __restrict__ C,
    int M, int N, int K, const float* __restrict__ bias_v, const float* __restrict__ extra)
{
    __shared__ float As[64][33];
    __shared__ float Bs[32][64];
    int tx = threadIdx.x & 15, ty = threadIdx.x >> 4;
    int j0 = blockIdx.x * 64, i0 = blockIdx.y * 64;
    float acc[4][4] = {};
    for (int kt = 0; kt < K; kt += 32) {
#pragma unroll
        for (int u = 0; u < 2; u++) {
            int idx = threadIdx.x * 2 + u;
            int r = idx >> 3, c4 = (idx & 7) * 4;
            float4 a = *(const float4*)(A + (size_t)(i0 + r) * K + kt + c4);
            As[r][c4] = a.x; As[r][c4+1] = a.y; As[r][c4+2] = a.z; As[r][c4+3] = a.w;
            int rb = idx >> 4, cb4 = (idx & 15) * 4;
            *(float4*)&Bs[rb][cb4] = *(const float4*)(B + (size_t)(kt + rb) * N + j0 + cb4);
        }
        __syncthreads();
#pragma unroll
        for (int kk = 0; kk < 32; kk++) {
            float a0 = As[ty*4][kk], a1 = As[ty*4+1][kk], a2 = As[ty*4+2][kk], a3 = As[ty*4+3][kk];
            float4 b = *(float4*)&Bs[kk][tx * 4];
            acc[0][0]+=a0*b.x; acc[0][1]+=a0*b.y; acc[0][2]+=a0*b.z; acc[0][3]+=a0*b.w;
            acc[1][0]+=a1*b.x; acc[1][1]+=a1*b.y; acc[1][2]+=a1*b.z; acc[1][3]+=a1*b.w;
            acc[2][0]+=a2*b.x; acc[2][1]+=a2*b.y; acc[2][2]+=a2*b.z; acc[2][3]+=a2*b.w;
            acc[3][0]+=a3*b.x; acc[3][1]+=a3*b.y; acc[3][2]+=a3*b.z; acc[3][3]+=a3*b.w;
        }
        __syncthreads();
    }
#pragma unroll
    for (int mm = 0; mm < 4; mm++) {
        int i = i0 + ty * 4 + mm, j = j0 + tx * 4;
        float vv[4] = {acc[mm][0], acc[mm][1], acc[mm][2], acc[mm][3]};
#pragma unroll
        for (int n = 0; n < 4; n++) {
            float v = vv[n]; int jc = j + n;
            if (EPI == 1) {
                if (jc >= 1152) { v += bias_v[jc - 1152]; v = 1.f / (1.f + __expf(-v)); }
            } else if (EPI == 2) {
                v = fmaxf(v + bias_v[jc], 0.f);
            } else if (EPI == 3) {
                v = v + bias_v[jc] + extra[(size_t)i * N + jc];
            }
            vv[n] = v;
        }
        float4 r; r.x = vv[0]; r.y = vv[1]; r.z = vv[2]; r.w = vv[3];
        *(float4*)(C + (size_t)i * N + j) = r;
    }
}

// ---------- RoPE on q,k slices (in place), double trig ----------
__global__ __launch_bounds__(256) void rope_kernel(const float* __restrict__ pos)
{
    int idx = blockIdx.x * 256 + threadIdx.x;
    if (idx >= NT * NH * 24) return;
    int t = idx % 24, h = (idx / 24) % NH, i = idx / (24 * NH);
    double invf = exp(-(double)t * (9.210340371976184 / 24.0));
    double th = (double)pos[i] * invf;
    float c = (float)cos(th), s = (float)sin(th);
    size_t bq = (size_t)i * DQKV + h * DHD;
    float x1 = g_s.qkvg[bq + t], x2 = g_s.qkvg[bq + 24 + t];
    g_s.qkvg[bq + t] = x1 * c - x2 * s;
    g_s.qkvg[bq + 24 + t] = x1 * s + x2 * c;
    size_t bk = bq + 384;
    x1 = g_s.qkvg[bk + t]; x2 = g_s.qkvg[bk + 24 + t];
    g_s.qkvg[bk + t] = x1 * c - x2 * s;
    g_s.qkvg[bk + 24 + t] = x1 * s + x2 * c;
}

// ---------- FUSED attention: S=qk*scale+bterm+mask -> online softmax -> P@V -> gate ----------
__global__ __launch_bounds__(256) void attn_kernel(const float* __restrict__ mask)
{
    __shared__ float Qs[64][49];
    __shared__ float Kt[48][68];
    __shared__ float Vs[64][49];
    __shared__ float Ps[64][68];
    int h = blockIdx.x;
    int i0 = blockIdx.y * 64;
    int tx = threadIdx.x & 15, ty = threadIdx.x >> 4;

    for (int u = threadIdx.x; u < 64 * 48; u += 256) {
        int r = u / 48, d = u % 48;
        Qs[r][d] = g_s.qkvg[(size_t)(i0 + r) * DQKV + h * DHD + d];
    }
    float acc[4][3] = {};
    float Lp[4] = {0.f, 0.f, 0.f, 0.f};
    float mrow[4], mi[4];
#pragma unroll
    for (int mm = 0; mm < 4; mm++) { mrow[mm] = -1e30f; mi[mm] = mask[i0 + ty * 4 + mm]; }
    __syncthreads();

    for (int j0 = 0; j0 < NT; j0 += 64) {
        for (int u = threadIdx.x; u < 64 * 48; u += 256) {
            int r = u / 48, d = u % 48;
            size_t rowb = (size_t)(j0 + r) * DQKV + h * DHD;
            Kt[d][r] = g_s.qkvg[rowb + 384 + d];
            Vs[r][d] = g_s.qkvg[rowb + 768 + d];
        }
        __syncthreads();

        float s[4][4] = {};
#pragma unroll
        for (int d = 0; d < 48; d++) {
            float a0 = Qs[ty*4][d], a1 = Qs[ty*4+1][d], a2 = Qs[ty*4+2][d], a3 = Qs[ty*4+3][d];
            float4 b = *(float4*)&Kt[d][tx * 4];
            s[0][0]+=a0*b.x; s[0][1]+=a0*b.y; s[0][2]+=a0*b.z; s[0][3]+=a0*b.w;
            s[1][0]+=a1*b.x; s[1][1]+=a1*b.y; s[1][2]+=a1*b.z; s[1][3]+=a1*b.w;
            s[2][0]+=a2*b.x; s[2][1]+=a2*b.y; s[2][2]+=a2*b.z; s[2][3]+=a2*b.w;
            s[3][0]+=a3*b.x; s[3][1]+=a3*b.y; s[3][2]+=a3*b.z; s[3][3]+=a3*b.w;
        }
        int j = j0 + tx * 4;
        float mj0 = mask[j], mj1 = mask[j+1], mj2 = mask[j+2], mj3 = mask[j+3];
        float tmax[4];
#pragma unroll
        for (int mm = 0; mm < 4; mm++) {
            size_t rowb = ((size_t)(i0 + ty * 4 + mm) * NH + h) * NT + j;
            float4 bt = *(const float4*)&g_s.bterm[rowb];
            s[mm][0] = s[mm][0]*SCALEQ + bt.x + INFV*(mi[mm]*mj0 - 1.f);
            s[mm][1] = s[mm][1]*SCALEQ + bt.y + INFV*(mi[mm]*mj1 - 1.f);
            s[mm][2] = s[mm][2]*SCALEQ + bt.z + INFV*(mi[mm]*mj2 - 1.f);
            s[mm][3] = s[mm][3]*SCALEQ + bt.w + INFV*(mi[mm]*mj3 - 1.f);
            tmax[mm] = fmaxf(fmaxf(s[mm][0], s[mm][1]), fmaxf(s[mm][2], s[mm][3]));
        }
#pragma unroll
        for (int o = 1; o < 16; o <<= 1) {
#pragma unroll
            for (int mm = 0; mm < 4; mm++)
                tmax[mm] = fmaxf(tmax[mm], __shfl_xor_sync(0xffffffffu, tmax[mm], o));
        }
#pragma unroll
        for (int mm = 0; mm < 4; mm++) {
            float mn = fmaxf(mrow[mm], tmax[mm]);
            float sc = __expf(mrow[mm] - mn);
            mrow[mm] = mn;
            Lp[mm] *= sc;
            acc[mm][0] *= sc; acc[mm][1] *= sc; acc[mm][2] *= sc;
            float p0 = __expf(s[mm][0] - mn), p1 = __expf(s[mm][1] - mn);
            float p2 = __expf(s[mm][2] - mn), p3 = __expf(s[mm][3] - mn);
            Lp[mm] += p0 + p1 + p2 + p3;
            float4 pv; pv.x = p0; pv.y = p1; pv.z = p2; pv.w = p3;
            *(float4*)&Ps[ty * 4 + mm][tx * 4] = pv;
        }
        __syncthreads();
#pragma unroll 4
        for (int kk = 0; kk < 64; kk++) {
            float b0 = Vs[kk][tx*3], b1 = Vs[kk][tx*3+1], b2 = Vs[kk][tx*3+2];
#pragma unroll
            for (int mm = 0; mm < 4; mm++) {
                float a = Ps[ty * 4 + mm][kk];
                acc[mm][0] += a * b0; acc[mm][1] += a * b1; acc[mm][2] += a * b2;
            }
        }
        __syncthreads();
    }
#pragma unroll
    for (int o = 1; o < 16; o <<= 1) {
#pragma unroll
        for (int mm = 0; mm < 4; mm++)
            Lp[mm] += __shfl_xor_sync(0xffffffffu, Lp[mm], o);
    }
#pragma unroll
    for (int mm = 0; mm < 4; mm++) {
        float inv = 1.f / Lp[mm];
        int i = i0 + ty * 4 + mm;
#pragma unroll
        for (int n = 0; n < 3; n++) {
            int d = tx * 3 + n;
            float gate = g_s.qkvg[(size_t)i * DQKV + 1152 + h * DHD + d];
            g_s.gated[(size_t)i * (NH * DHD) + h * DHD + d] = gate * acc[mm][n] * inv;
        }
    }
}

extern "C" void kernel_launch(void* const* d_in, const int* in_sizes, int n_in,
                              void* d_out, int out_size)
{
    const float* node   = (const float*)d_in[0];
    const float* edge   = (const float*)d_in[1];
    const float* bias   = (const float*)d_in[2];
    const float* pos    = (const float*)d_in[3];
    const float* mask   = (const float*)d_in[4];
    const float* g_node = (const float*)d_in[5];
    const float* b_node = (const float*)d_in[6];
    const float* g_edge = (const float*)d_in[7];
    const float* b_edge = (const float*)d_in[8];
    const float* W_bias = (const float*)d_in[9];
    const float* Wq     = (const float*)d_in[10];
    const float* Wk     = (const float*)d_in[11];
    const float* Wv     = (const float*)d_in[12];
    const float* Wb     = (const float*)d_in[13];
    const float* Wg     = (const float*)d_in[14];
    const float* bg     = (const float*)d_in[15];
    const float* Wo     = (const float*)d_in[16];
    const float* g_ff   = (const float*)d_in[17];
    const float* b_ff   = (const float*)d_in[18];
    const float* W1     = (const float*)d_in[19];
    const float* b1     = (const float*)d_in[20];
    const float* W2     = (const float*)d_in[21];
    const float* b2     = (const float*)d_in[22];
    float* out = (float*)d_out;

    Scratch* s = nullptr;
    cudaGetSymbolAddress((void**)&s, g_s);

    precompute_kernel<<<1, 256>>>(g_edge, b_edge, W_bias, Wb);               // 1
    packw_kernel<<<(DN * DQKV + 255) / 256, 256>>>(Wq, Wk, Wv, Wg);          // 2
    ln_kernel<<<NT / 8, 256>>>(node, g_node, b_node, s->node_n);             // 3
    bterm_kernel<<<(NT * NT) / 32, 256>>>(edge, bias);                       // 4 (profiled slot)
    gemm_kernel<1><<<dim3(DQKV / 64, NT / 64), 256>>>(s->node_n, s->Wcat, s->qkvg,
                                                      NT, DQKV, DN, bg, nullptr);  // 5
    rope_kernel<<<(NT * NH * 24 + 255) / 256, 256>>>(pos);                   // 6
    attn_kernel<<<dim3(NH, NT / 64), 256>>>(mask);                           // 7
    gemm_kernel<0><<<dim3(DN / 64, NT / 64), 256>>>(s->gated, Wo, s->attnout,
                                                    NT, DN, NH * DHD, nullptr, nullptr); // 8
    ln_kernel<<<NT / 8, 256>>>(s->attnout, g_ff, b_ff, s->h0);               // 9
    gemm_kernel<2><<<dim3(2 * DN / 64, NT / 64), 256>>>(s->h0, W1, s->h1,
                                                        NT, 2 * DN, DN, b1, nullptr);    // 10
    gemm_kernel<3><<<dim3(DN / 64, NT / 64), 256>>>(s->h1, W2, out,
                                                    NT, DN, 2 * DN, b2, node);           // 11
}